// round 3
// baseline (speedup 1.0000x reference)
#include <cuda_runtime.h>
#include <math.h>
#include <stdint.h>

// ---------------------------------------------------------------------------
// Problem constants (fixed shapes for this problem instance)
// ---------------------------------------------------------------------------
#define BATCH 2
#define SEQ   2048
#define DIM   2048
#define NH    16
#define DK    128
#define DV    128
#define MTOT  (BATCH * SEQ)          // 4096 rows
#define NELEM (MTOT * DIM)           // 8388608

// ---------------------------------------------------------------------------
// Device scratch (static __device__ arrays -- allocation-free per the rules)
// ---------------------------------------------------------------------------
__device__ float g_qpre[NELEM];
__device__ float g_kpre[NELEM];
__device__ float g_vpre[NELEM];
__device__ float g_q[NELEM];
__device__ float g_k[NELEM];
__device__ float g_v[NELEM];
__device__ float g_gate[NELEM];
__device__ float g_g[NELEM];         // gpre, then gexp written in-place
__device__ float g_o[NELEM];         // o, then gated-normed o in-place
__device__ float g_f1[MTOT * DV];
__device__ float g_beta[MTOT * NH];

// ---------------------------------------------------------------------------
// SGEMM: C[M,N] = A[M,K] @ B[K,N], all row-major fp32.
// 128x128 block tile, BK=8, 256 threads, 8x8 per thread, register prefetch.
// M,N multiples of 128; K multiple of 8.
// ---------------------------------------------------------------------------
#define GBM 128
#define GBN 128
#define GBK 8

__global__ __launch_bounds__(256) void sgemm_kernel(
    const float* __restrict__ A, const float* __restrict__ B,
    float* __restrict__ C, int M, int N, int K)
{
    __shared__ float As[GBK][GBM];
    __shared__ float Bs[GBK][GBN];

    const int tid = threadIdx.x;
    const int bm = blockIdx.y * GBM;
    const int bn = blockIdx.x * GBN;

    // A tile loader: 128 rows x 8 cols -> 256 float4 (2 per row)
    const int aRow = tid >> 1;
    const int aCol = (tid & 1) * 4;
    // B tile loader: 8 rows x 128 cols -> 256 float4
    const int bRow = tid >> 5;
    const int bCol = (tid & 31) * 4;

    const int tr = (tid / 16) * 8;   // 0..120
    const int tc = (tid % 16) * 8;   // 0..120

    const float* Ap = A + (size_t)(bm + aRow) * K + aCol;
    const float* Bp = B + (size_t)bRow * N + bn + bCol;

    float acc[8][8];
#pragma unroll
    for (int i = 0; i < 8; i++)
#pragma unroll
        for (int j = 0; j < 8; j++) acc[i][j] = 0.f;

    float4 av = *(const float4*)(Ap);
    float4 bv = *(const float4*)(Bp);

    for (int k0 = 0; k0 < K; k0 += GBK) {
        // store current tile to shared
        As[aCol + 0][aRow] = av.x;
        As[aCol + 1][aRow] = av.y;
        As[aCol + 2][aRow] = av.z;
        As[aCol + 3][aRow] = av.w;
        *(float4*)&Bs[bRow][bCol] = bv;
        __syncthreads();

        // prefetch next tile into registers
        if (k0 + GBK < K) {
            av = *(const float4*)(Ap + k0 + GBK);
            bv = *(const float4*)(Bp + (size_t)(k0 + GBK) * N);
        }

#pragma unroll
        for (int kk = 0; kk < GBK; kk++) {
            float a[8], b[8];
            *(float4*)&a[0] = *(const float4*)&As[kk][tr];
            *(float4*)&a[4] = *(const float4*)&As[kk][tr + 4];
            *(float4*)&b[0] = *(const float4*)&Bs[kk][tc];
            *(float4*)&b[4] = *(const float4*)&Bs[kk][tc + 4];
#pragma unroll
            for (int i = 0; i < 8; i++)
#pragma unroll
                for (int j = 0; j < 8; j++) acc[i][j] += a[i] * b[j];
        }
        __syncthreads();
    }

#pragma unroll
    for (int i = 0; i < 8; i++) {
        float* cp = C + (size_t)(bm + tr + i) * N + bn + tc;
        *(float4*)(cp)     = *(float4*)&acc[i][0];
        *(float4*)(cp + 4) = *(float4*)&acc[i][4];
    }
}

// ---------------------------------------------------------------------------
// beta = sigmoid(x @ Wb)   x:[MTOT,DIM], Wb:[DIM,NH] -> [MTOT,NH]
// one block (128 threads) per row
// ---------------------------------------------------------------------------
__global__ __launch_bounds__(128) void beta_kernel(
    const float* __restrict__ x, const float* __restrict__ Wb,
    float* __restrict__ beta)
{
    const int m = blockIdx.x;
    const int tid = threadIdx.x;
    const float* xr = x + (size_t)m * DIM;

    float acc[NH];
#pragma unroll
    for (int h = 0; h < NH; h++) acc[h] = 0.f;

    for (int k = tid; k < DIM; k += 128) {
        float xv = xr[k];
        const float* wr = Wb + (size_t)k * NH;
#pragma unroll
        for (int h = 0; h < NH; h++) acc[h] += xv * wr[h];
    }

    __shared__ float sh[128 * NH];
#pragma unroll
    for (int h = 0; h < NH; h++) sh[tid * NH + h] = acc[h];
    __syncthreads();

    if (tid < NH) {
        float s = 0.f;
        for (int i = 0; i < 128; i++) s += sh[i * NH + tid];
        beta[(size_t)m * NH + tid] = 1.f / (1.f + expf(-s));
    }
}

// ---------------------------------------------------------------------------
// Causal depthwise conv (K=4) + SiLU, optional per-head L2 norm.
// Block: 128 threads over channels of ONE head; tile of 32 timesteps.
// Grid: (SEQ/32, DIM/128, BATCH)
// ---------------------------------------------------------------------------
template <bool NORM>
__global__ __launch_bounds__(128) void conv_kernel(
    const float* __restrict__ xin, const float* __restrict__ w,
    float* __restrict__ out)
{
    const int TT = 32;
    const int t0 = blockIdx.x * TT;
    const int c0 = blockIdx.y * 128;
    const int b  = blockIdx.z;
    const int tid = threadIdx.x;
    const int c = c0 + tid;

    __shared__ float xsh[TT + 3][128];
    __shared__ float ysh[TT][128];
    __shared__ float rns[TT];

    const float* xb = xin + ((size_t)b * SEQ) * DIM + c;
#pragma unroll
    for (int r = 0; r < TT + 3; r++) {
        int t = t0 - 3 + r;
        xsh[r][tid] = (t >= 0) ? xb[(size_t)t * DIM] : 0.f;
    }
    float4 wv = *(const float4*)(w + (size_t)c * 4);
    __syncthreads();

    float yreg[TT];
#pragma unroll
    for (int tt = 0; tt < TT; tt++) {
        float y = xsh[tt][tid] * wv.x + xsh[tt + 1][tid] * wv.y
                + xsh[tt + 2][tid] * wv.z + xsh[tt + 3][tid] * wv.w;
        y = y / (1.f + expf(-y));    // SiLU
        yreg[tt] = y;
        if (NORM) ysh[tt][tid] = y;
    }

    if (NORM) {
        __syncthreads();
        const int wid = tid >> 5, lane = tid & 31;
        for (int tt = wid; tt < TT; tt += 4) {
            float a0 = ysh[tt][lane],      a1 = ysh[tt][lane + 32];
            float a2 = ysh[tt][lane + 64], a3 = ysh[tt][lane + 96];
            float s = a0 * a0 + a1 * a1 + a2 * a2 + a3 * a3;
#pragma unroll
            for (int off = 16; off > 0; off >>= 1)
                s += __shfl_xor_sync(0xFFFFFFFFu, s, off);
            if (lane == 0) rns[tt] = rsqrtf(s + 1e-6f);
        }
        __syncthreads();
    }

    float* ob = out + ((size_t)b * SEQ) * DIM + c;
#pragma unroll
    for (int tt = 0; tt < TT; tt++) {
        float y = yreg[tt];
        if (NORM) y *= rns[tt];
        ob[(size_t)(t0 + tt) * DIM] = y;
    }
}

// ---------------------------------------------------------------------------
// KDA gate: g <- exp(-exp(A_log[h]) * softplus(g + dt_bias[c]))   (in-place)
// ---------------------------------------------------------------------------
__global__ void gexp_kernel(float* __restrict__ g,
                            const float* __restrict__ A_log,
                            const float* __restrict__ dt_bias, int n)
{
    int i = blockIdx.x * blockDim.x + threadIdx.x;
    if (i >= n) return;
    int c = i & (DIM - 1);
    int h = c >> 7;
    float a = -expf(A_log[h]);
    float u = g[i] + dt_bias[c];
    float sp = (u > 20.f) ? u : log1pf(expf(u));
    g[i] = expf(a * sp);
}

// ---------------------------------------------------------------------------
// Sequential delta-rule scan. One block per (b,h); thread tid owns state
// column S[:, tid] (128 fp32 registers). q/k/gexp broadcast via shared.
// ---------------------------------------------------------------------------
__global__ __launch_bounds__(128) void scan_kernel(
    const float* __restrict__ q, const float* __restrict__ k,
    const float* __restrict__ v, const float* __restrict__ ge,
    const float* __restrict__ beta, float* __restrict__ o)
{
    const int b = blockIdx.x / NH;
    const int h = blockIdx.x % NH;
    const int tid = threadIdx.x;

    __shared__ float qs[128], ks[128], gs[128];

    float S[128];
#pragma unroll
    for (int i = 0; i < 128; i++) S[i] = 0.f;

    const float scale = 0.08838834764831845f;   // 128^-0.5

    for (int t = 0; t < SEQ; t++) {
        size_t base = ((size_t)(b * SEQ + t) * NH + h) * (size_t)DK;
        float qv = q[base + tid];
        float kl = k[base + tid];
        float gl = ge[base + tid];
        float vt = v[base + tid];
        float bt = beta[(size_t)(b * SEQ + t) * NH + h];

        __syncthreads();                // previous iteration's reads complete
        qs[tid] = qv; ks[tid] = kl; gs[tid] = gl;
        __syncthreads();

        float kv0 = 0.f, kv1 = 0.f, kv2 = 0.f, kv3 = 0.f;
#pragma unroll
        for (int i = 0; i < 128; i += 4) {
            S[i + 0] *= gs[i + 0]; kv0 += ks[i + 0] * S[i + 0];
            S[i + 1] *= gs[i + 1]; kv1 += ks[i + 1] * S[i + 1];
            S[i + 2] *= gs[i + 2]; kv2 += ks[i + 2] * S[i + 2];
            S[i + 3] *= gs[i + 3]; kv3 += ks[i + 3] * S[i + 3];
        }
        float upd = (vt - ((kv0 + kv1) + (kv2 + kv3))) * bt;

        float o0 = 0.f, o1 = 0.f, o2 = 0.f, o3 = 0.f;
#pragma unroll
        for (int i = 0; i < 128; i += 4) {
            S[i + 0] += ks[i + 0] * upd; o0 += qs[i + 0] * S[i + 0];
            S[i + 1] += ks[i + 1] * upd; o1 += qs[i + 1] * S[i + 1];
            S[i + 2] += ks[i + 2] * upd; o2 += qs[i + 2] * S[i + 2];
            S[i + 3] += ks[i + 3] * upd; o3 += qs[i + 3] * S[i + 3];
        }
        o[base + tid] = ((o0 + o1) + (o2 + o3)) * scale;
    }
}

// ---------------------------------------------------------------------------
// Epilogue: per (b,t,h) gated RMSNorm (in-place on o):
//   on = o * rsqrt(mean(o^2)+1e-5) * o_norm_w * silu(gate + bg)
// Grid: (MTOT, NH), 128 threads
// ---------------------------------------------------------------------------
__global__ __launch_bounds__(128) void epilogue_kernel(
    float* __restrict__ o, const float* __restrict__ gate,
    const float* __restrict__ bg, const float* __restrict__ onw)
{
    const int m = blockIdx.x;
    const int h = blockIdx.y;
    const int tid = threadIdx.x;
    size_t idx = ((size_t)m * NH + h) * (size_t)DV + tid;

    float ov = o[idx];
    float s = ov * ov;
#pragma unroll
    for (int off = 16; off > 0; off >>= 1)
        s += __shfl_xor_sync(0xFFFFFFFFu, s, off);

    __shared__ float ws[4];
    const int wid = tid >> 5, lane = tid & 31;
    if (lane == 0) ws[wid] = s;
    __syncthreads();
    float tot = ws[0] + ws[1] + ws[2] + ws[3];

    float r = rsqrtf(tot * (1.f / 128.f) + 1e-5f);
    float gv = gate[idx] + bg[h * DV + tid];
    float sig = 1.f / (1.f + expf(-gv));
    o[idx] = ov * r * onw[tid] * (gv * sig);
}

// ---------------------------------------------------------------------------
// kernel_launch
// ---------------------------------------------------------------------------
extern "C" void kernel_launch(void* const* d_in, const int* in_sizes, int n_in,
                              void* d_out, int out_size)
{
    const float* x       = (const float*)d_in[0];
    const float* Wq      = (const float*)d_in[1];
    const float* Wk      = (const float*)d_in[2];
    const float* Wv      = (const float*)d_in[3];
    const float* conv_q  = (const float*)d_in[4];
    const float* conv_k  = (const float*)d_in[5];
    const float* conv_v  = (const float*)d_in[6];
    const float* Wf1     = (const float*)d_in[7];
    const float* Wf2     = (const float*)d_in[8];
    const float* Wb      = (const float*)d_in[9];
    const float* A_log   = (const float*)d_in[10];
    const float* dt_bias = (const float*)d_in[11];
    const float* Wg      = (const float*)d_in[12];
    const float* bg      = (const float*)d_in[13];
    const float* o_norm_w= (const float*)d_in[14];
    const float* Wo      = (const float*)d_in[15];
    float* out = (float*)d_out;

    float *qpre, *kpre, *vpre, *qb, *kb, *vb, *gateb, *gb, *ob, *f1b, *betab;
    cudaGetSymbolAddress((void**)&qpre,  g_qpre);
    cudaGetSymbolAddress((void**)&kpre,  g_kpre);
    cudaGetSymbolAddress((void**)&vpre,  g_vpre);
    cudaGetSymbolAddress((void**)&qb,    g_q);
    cudaGetSymbolAddress((void**)&kb,    g_k);
    cudaGetSymbolAddress((void**)&vb,    g_v);
    cudaGetSymbolAddress((void**)&gateb, g_gate);
    cudaGetSymbolAddress((void**)&gb,    g_g);
    cudaGetSymbolAddress((void**)&ob,    g_o);
    cudaGetSymbolAddress((void**)&f1b,   g_f1);
    cudaGetSymbolAddress((void**)&betab, g_beta);

    dim3 gBig(DIM / GBN, MTOT / GBM);       // (16, 32)
    dim3 gF1(DV / GBN, MTOT / GBM);         // (1, 32)

    // --- projections ---
    sgemm_kernel<<<gBig, 256>>>(x, Wq, qpre, MTOT, DIM, DIM);
    sgemm_kernel<<<gBig, 256>>>(x, Wk, kpre, MTOT, DIM, DIM);
    sgemm_kernel<<<gBig, 256>>>(x, Wv, vpre, MTOT, DIM, DIM);
    sgemm_kernel<<<gBig, 256>>>(x, Wg, gateb, MTOT, DIM, DIM);
    sgemm_kernel<<<gF1, 256>>>(x, Wf1, f1b, MTOT, DV, DIM);
    sgemm_kernel<<<gBig, 256>>>(f1b, Wf2, gb, MTOT, DIM, DV);

    beta_kernel<<<MTOT, 128>>>(x, Wb, betab);

    // --- conv + silu (+ l2norm for q,k) ---
    dim3 gConv(SEQ / 32, DIM / 128, BATCH);
    conv_kernel<true ><<<gConv, 128>>>(qpre, conv_q, qb);
    conv_kernel<true ><<<gConv, 128>>>(kpre, conv_k, kb);
    conv_kernel<false><<<gConv, 128>>>(vpre, conv_v, vb);

    // --- decay gates ---
    gexp_kernel<<<NELEM / 256, 256>>>(gb, A_log, dt_bias, NELEM);

    // --- sequential delta-rule scan ---
    scan_kernel<<<BATCH * NH, 128>>>(qb, kb, vb, gb, betab, ob);

    // --- gated RMSNorm epilogue (in-place on o) ---
    dim3 gEpi(MTOT, NH);
    epilogue_kernel<<<gEpi, 128>>>(ob, gateb, bg, o_norm_w);

    // --- output projection ---
    sgemm_kernel<<<gBig, 256>>>(ob, Wo, out, MTOT, DIM, DIM);
}

// round 7
// speedup vs baseline: 2.6090x; 2.6090x over previous
#include <cuda_runtime.h>
#include <cuda_bf16.h>
#include <math.h>
#include <stdint.h>

// ---------------------------------------------------------------------------
// Problem constants
// ---------------------------------------------------------------------------
#define BATCH 2
#define SEQ   2048
#define DIM   2048
#define NH    16
#define DK    128
#define DV    128
#define MTOT  (BATCH * SEQ)          // 4096
#define NELEM (MTOT * DIM)           // 8388608
#define WSZ   (DIM * DIM)            // 4194304

// ---------------------------------------------------------------------------
// Device scratch
// ---------------------------------------------------------------------------
__device__ float g_qpre[NELEM];
__device__ float g_kpre[NELEM];
__device__ float g_vpre[NELEM];
__device__ float g_q[NELEM];
__device__ float g_k[NELEM];
__device__ float g_v[NELEM];
__device__ float g_gate[NELEM];
__device__ float g_g[NELEM];
__device__ float g_o[NELEM];
__device__ float g_f1[MTOT * DV];
__device__ float g_beta[MTOT * NH];

// bf16 split buffers (hi/lo)
__device__ __nv_bfloat16 g_xh[NELEM],  g_xl[NELEM];
__device__ __nv_bfloat16 g_oh[NELEM],  g_ol[NELEM];
__device__ __nv_bfloat16 g_wqh[WSZ],   g_wql[WSZ];
__device__ __nv_bfloat16 g_wkh[WSZ],   g_wkl[WSZ];
__device__ __nv_bfloat16 g_wvh[WSZ],   g_wvl[WSZ];
__device__ __nv_bfloat16 g_wgh[WSZ],   g_wgl[WSZ];
__device__ __nv_bfloat16 g_woh[WSZ],   g_wol[WSZ];
__device__ __nv_bfloat16 g_wf1h[DIM*DV], g_wf1l[DIM*DV];
__device__ __nv_bfloat16 g_wf2h[DV*DIM], g_wf2l[DV*DIM];
__device__ __nv_bfloat16 g_f1h[MTOT*DV], g_f1l[MTOT*DV];

// ---------------------------------------------------------------------------
// Baseline-ISA PTX helpers (sm_80-era: mma.sync / ldmatrix / cp.async only)
// ---------------------------------------------------------------------------
__device__ __forceinline__ uint32_t smem_u32(const void* p) {
    uint32_t a;
    asm("{ .reg .u64 t; cvta.to.shared.u64 t, %1; cvt.u32.u64 %0, t; }"
        : "=r"(a) : "l"(p));
    return a;
}

#define CP16(dst, src) \
    asm volatile("cp.async.cg.shared.global [%0], [%1], 16;" \
                 :: "r"(dst), "l"(src))
#define CP_COMMIT() asm volatile("cp.async.commit_group;" ::: "memory")
#define CP_WAIT0()  asm volatile("cp.async.wait_group 0;" ::: "memory")
#define CP_WAIT1()  asm volatile("cp.async.wait_group 1;" ::: "memory")

#define LDSM4(R, addr)                                                         \
    asm volatile("ldmatrix.sync.aligned.m8n8.x4.shared.b16 {%0,%1,%2,%3}, [%4];" \
        : "=r"((R)[0]), "=r"((R)[1]), "=r"((R)[2]), "=r"((R)[3]) : "r"(addr))

#define LDSM4T(R, addr)                                                        \
    asm volatile("ldmatrix.sync.aligned.m8n8.x4.trans.shared.b16 {%0,%1,%2,%3}, [%4];" \
        : "=r"((R)[0]), "=r"((R)[1]), "=r"((R)[2]), "=r"((R)[3]) : "r"(addr))

#define MMA16816(C4, A4, b0, b1)                                               \
    asm volatile("mma.sync.aligned.m16n8k16.row.col.f32.bf16.bf16.f32 "        \
        "{%0,%1,%2,%3},{%4,%5,%6,%7},{%8,%9},{%0,%1,%2,%3};"                   \
        : "+f"((C4)[0]), "+f"((C4)[1]), "+f"((C4)[2]), "+f"((C4)[3])           \
        : "r"((A4)[0]), "r"((A4)[1]), "r"((A4)[2]), "r"((A4)[3]),              \
          "r"(b0), "r"(b1))

// ---------------------------------------------------------------------------
// Split fp32 -> bf16 hi + bf16 lo
// ---------------------------------------------------------------------------
__global__ void split_kernel(const float4* __restrict__ in,
                             __nv_bfloat162* __restrict__ hi,
                             __nv_bfloat162* __restrict__ lo, int n4)
{
    int i = blockIdx.x * blockDim.x + threadIdx.x;
    if (i >= n4) return;
    float4 a = in[i];
    __nv_bfloat16 hx = __float2bfloat16(a.x);
    __nv_bfloat16 hy = __float2bfloat16(a.y);
    __nv_bfloat16 hz = __float2bfloat16(a.z);
    __nv_bfloat16 hw = __float2bfloat16(a.w);
    float rx = a.x - __bfloat162float(hx);
    float ry = a.y - __bfloat162float(hy);
    float rz = a.z - __bfloat162float(hz);
    float rw = a.w - __bfloat162float(hw);
    hi[2 * i]     = __halves2bfloat162(hx, hy);
    hi[2 * i + 1] = __halves2bfloat162(hz, hw);
    lo[2 * i]     = __halves2bfloat162(__float2bfloat16(rx), __float2bfloat16(ry));
    lo[2 * i + 1] = __halves2bfloat162(__float2bfloat16(rz), __float2bfloat16(rw));
}

// ---------------------------------------------------------------------------
// bf16-split tensor GEMM via mma.sync (HMMA): C[M,N] = A[M,K] @ B[K,N]
// 128x128 CTA tile, BK=32, 256 threads (8 warps, warp tile 64x32),
// cp.async double-buffered, ldmatrix(.trans) operand loads.
// A smem: [128][40] bf16 (pad 8)  -> conflict-free ldmatrix
// B smem: [32][136] bf16 (pad 8)  -> conflict-free ldmatrix.trans
// 3 passes per k-step: Ah*Bh + Ah*Bl + Al*Bh
// ---------------------------------------------------------------------------
#define BKC 32
#define A_STR 40                       // bf16 units (80 bytes)
#define B_STR 136                      // bf16 units (272 bytes)
#define SA_SLOT (128 * A_STR * 2)      // 10240 bytes per A tensor tile
#define SB_SLOT (BKC * B_STR * 2)      // 8704 bytes per B tensor tile
#define ABYTES (4 * SA_SLOT)           // 40960 (2 bufs x hi/lo)
#define OFF_A(buf, hl) ((buf) * 2 * SA_SLOT + (hl) * SA_SLOT)
#define OFF_B(buf, hl) (ABYTES + (buf) * 2 * SB_SLOT + (hl) * SB_SLOT)
#define GEMM_SMEM (ABYTES + 4 * SB_SLOT)   // 75776 bytes

__device__ __forceinline__ void gemm_load_chunk(
    uint32_t sb, int buf,
    const __nv_bfloat16* __restrict__ Ah, const __nv_bfloat16* __restrict__ Al,
    const __nv_bfloat16* __restrict__ Bh, const __nv_bfloat16* __restrict__ Bl,
    int m0, int n0, int k0, int K, int N, int tid)
{
#pragma unroll
    for (int r = 0; r < 2; r++) {
        int i = tid + (r << 8);
        int row = i >> 2;
        int kc  = (i & 3) << 3;      // bf16 units
        uint32_t da = sb + OFF_A(buf, 0) + row * (A_STR * 2) + kc * 2;
        CP16(da, (const void*)(Ah + (size_t)(m0 + row) * K + k0 + kc));
        uint32_t dl = da + SA_SLOT;
        CP16(dl, (const void*)(Al + (size_t)(m0 + row) * K + k0 + kc));
    }
#pragma unroll
    for (int r = 0; r < 2; r++) {
        int i = tid + (r << 8);
        int krow = i >> 4;
        int nc   = (i & 15) << 3;
        uint32_t db = sb + OFF_B(buf, 0) + krow * (B_STR * 2) + nc * 2;
        CP16(db, (const void*)(Bh + (size_t)(k0 + krow) * N + n0 + nc));
        uint32_t dl = db + SB_SLOT;
        CP16(dl, (const void*)(Bl + (size_t)(k0 + krow) * N + n0 + nc));
    }
}

__global__ void __launch_bounds__(256)
tgemm_kernel(const __nv_bfloat16* __restrict__ Ah,
             const __nv_bfloat16* __restrict__ Al,
             const __nv_bfloat16* __restrict__ Bh,
             const __nv_bfloat16* __restrict__ Bl,
             float* __restrict__ C, int M, int N, int K)
{
    extern __shared__ char smem[];
    const uint32_t sb = smem_u32(smem);
    const int tid  = threadIdx.x;
    const int lane = tid & 31;
    const int wid  = tid >> 5;
    const int wm0  = (wid >> 2) * 64;   // warp row offset in CTA tile
    const int wn0  = (wid & 3) * 32;    // warp col offset
    const int m0 = blockIdx.y * 128;
    const int n0 = blockIdx.x * 128;

    float acc[4][4][4];
#pragma unroll
    for (int a = 0; a < 4; a++)
#pragma unroll
        for (int b = 0; b < 4; b++)
#pragma unroll
            for (int c = 0; c < 4; c++) acc[a][b][c] = 0.f;

    const int nch = K / BKC;

    gemm_load_chunk(sb, 0, Ah, Al, Bh, Bl, m0, n0, 0, K, N, tid);
    CP_COMMIT();

    for (int ch = 0; ch < nch; ch++) {
        const int buf = ch & 1;
        if (ch + 1 < nch) {
            gemm_load_chunk(sb, buf ^ 1, Ah, Al, Bh, Bl,
                            m0, n0, (ch + 1) * BKC, K, N, tid);
            CP_COMMIT();
            CP_WAIT1();
        } else {
            CP_WAIT0();
        }
        __syncthreads();

        const uint32_t aBase = sb + OFF_A(buf, 0);
        const uint32_t bBase = sb + OFF_B(buf, 0);

#pragma unroll
        for (int kk = 0; kk < 2; kk++) {
            const int kb = kk * 16;
            uint32_t Ahf[4][4], Alf[4][4], Bhf[2][4], Blf[2][4];

            // A frags: row = wm0 + mb*16 + (lane&15); kcol = kb + (lane>>4)*8
            const int arow = wm0 + (lane & 15);
            const uint32_t kcol = (uint32_t)(kb + ((lane >> 4) << 3)) * 2;
#pragma unroll
            for (int mb = 0; mb < 4; mb++) {
                uint32_t ad = aBase + (uint32_t)(arow + mb * 16) * (A_STR * 2) + kcol;
                LDSM4(Ahf[mb], ad);
                LDSM4(Alf[mb], ad + SA_SLOT);
            }
            // B frags (trans): krow = kb + (lane&15); nseg = wn0 + nb2*16 + (lane>>4)*8
            const int krow = kb + (lane & 15);
#pragma unroll
            for (int nb2 = 0; nb2 < 2; nb2++) {
                uint32_t nby = (uint32_t)(wn0 + nb2 * 16 + ((lane >> 4) << 3)) * 2;
                uint32_t bd = bBase + (uint32_t)krow * (B_STR * 2) + nby;
                LDSM4T(Bhf[nb2], bd);
                LDSM4T(Blf[nb2], bd + SB_SLOT);
            }

#pragma unroll
            for (int mb = 0; mb < 4; mb++) {
#pragma unroll
                for (int nb = 0; nb < 4; nb++) {
                    uint32_t bh0 = Bhf[nb >> 1][(nb & 1) << 1];
                    uint32_t bh1 = Bhf[nb >> 1][((nb & 1) << 1) | 1];
                    uint32_t bl0 = Blf[nb >> 1][(nb & 1) << 1];
                    uint32_t bl1 = Blf[nb >> 1][((nb & 1) << 1) | 1];
                    MMA16816(acc[mb][nb], Ahf[mb], bh0, bh1);
                    MMA16816(acc[mb][nb], Ahf[mb], bl0, bl1);
                    MMA16816(acc[mb][nb], Alf[mb], bh0, bh1);
                }
            }
        }
        __syncthreads();
    }

    // epilogue: direct fp32 stores (float2 per frag half)
#pragma unroll
    for (int mb = 0; mb < 4; mb++) {
#pragma unroll
        for (int nb = 0; nb < 4; nb++) {
            int r = m0 + wm0 + mb * 16 + (lane >> 2);
            int c = n0 + wn0 + nb * 8 + ((lane & 3) << 1);
            float2 v0 = make_float2(acc[mb][nb][0], acc[mb][nb][1]);
            float2 v1 = make_float2(acc[mb][nb][2], acc[mb][nb][3]);
            *(float2*)&C[(size_t)r * N + c]       = v0;
            *(float2*)&C[(size_t)(r + 8) * N + c] = v1;
        }
    }
}

// ---------------------------------------------------------------------------
// beta = sigmoid(x @ Wb)
// ---------------------------------------------------------------------------
__global__ __launch_bounds__(128) void beta_kernel(
    const float* __restrict__ x, const float* __restrict__ Wb,
    float* __restrict__ beta)
{
    const int m = blockIdx.x;
    const int tid = threadIdx.x;
    const float* xr = x + (size_t)m * DIM;

    float acc[NH];
#pragma unroll
    for (int h = 0; h < NH; h++) acc[h] = 0.f;

    for (int k = tid; k < DIM; k += 128) {
        float xv = xr[k];
        const float* wr = Wb + (size_t)k * NH;
#pragma unroll
        for (int h = 0; h < NH; h++) acc[h] += xv * wr[h];
    }

    __shared__ float sh[128 * NH];
#pragma unroll
    for (int h = 0; h < NH; h++) sh[tid * NH + h] = acc[h];
    __syncthreads();

    if (tid < NH) {
        float s = 0.f;
        for (int i = 0; i < 128; i++) s += sh[i * NH + tid];
        beta[(size_t)m * NH + tid] = 1.f / (1.f + expf(-s));
    }
}

// ---------------------------------------------------------------------------
// Causal depthwise conv (K=4) + SiLU (+ per-head L2 norm)
// ---------------------------------------------------------------------------
template <bool NORM>
__global__ __launch_bounds__(128) void conv_kernel(
    const float* __restrict__ xin, const float* __restrict__ w,
    float* __restrict__ out)
{
    const int TT = 32;
    const int t0 = blockIdx.x * TT;
    const int c0 = blockIdx.y * 128;
    const int b  = blockIdx.z;
    const int tid = threadIdx.x;
    const int c = c0 + tid;

    __shared__ float xsh[TT + 3][128];
    __shared__ float ysh[TT][128];
    __shared__ float rns[TT];

    const float* xb = xin + ((size_t)b * SEQ) * DIM + c;
#pragma unroll
    for (int r = 0; r < TT + 3; r++) {
        int t = t0 - 3 + r;
        xsh[r][tid] = (t >= 0) ? xb[(size_t)t * DIM] : 0.f;
    }
    float4 wv = *(const float4*)(w + (size_t)c * 4);
    __syncthreads();

    float yreg[TT];
#pragma unroll
    for (int tt = 0; tt < TT; tt++) {
        float y = xsh[tt][tid] * wv.x + xsh[tt + 1][tid] * wv.y
                + xsh[tt + 2][tid] * wv.z + xsh[tt + 3][tid] * wv.w;
        y = y / (1.f + expf(-y));
        yreg[tt] = y;
        if (NORM) ysh[tt][tid] = y;
    }

    if (NORM) {
        __syncthreads();
        const int wd = tid >> 5, lane = tid & 31;
        for (int tt = wd; tt < TT; tt += 4) {
            float a0 = ysh[tt][lane],      a1 = ysh[tt][lane + 32];
            float a2 = ysh[tt][lane + 64], a3 = ysh[tt][lane + 96];
            float s = a0 * a0 + a1 * a1 + a2 * a2 + a3 * a3;
#pragma unroll
            for (int off = 16; off > 0; off >>= 1)
                s += __shfl_xor_sync(0xFFFFFFFFu, s, off);
            if (lane == 0) rns[tt] = rsqrtf(s + 1e-6f);
        }
        __syncthreads();
    }

    float* ob = out + ((size_t)b * SEQ) * DIM + c;
#pragma unroll
    for (int tt = 0; tt < TT; tt++) {
        float y = yreg[tt];
        if (NORM) y *= rns[tt];
        ob[(size_t)(t0 + tt) * DIM] = y;
    }
}

// ---------------------------------------------------------------------------
// gexp
// ---------------------------------------------------------------------------
__global__ void gexp_kernel(float* __restrict__ g,
                            const float* __restrict__ A_log,
                            const float* __restrict__ dt_bias, int n)
{
    int i = blockIdx.x * blockDim.x + threadIdx.x;
    if (i >= n) return;
    int c = i & (DIM - 1);
    int h = c >> 7;
    float a = -expf(A_log[h]);
    float u = g[i] + dt_bias[c];
    float sp = (u > 20.f) ? u : log1pf(expf(u));
    g[i] = expf(a * sp);
}

// ---------------------------------------------------------------------------
// Delta-rule scan. 128 blocks = (b,h) x 4 column-groups. Block: 128 threads,
// thread = (col in group of 32, k-split of 4). S[32] in registers.
// ---------------------------------------------------------------------------
__global__ __launch_bounds__(128) void scan_kernel(
    const float* __restrict__ q, const float* __restrict__ k,
    const float* __restrict__ v, const float* __restrict__ ge,
    const float* __restrict__ beta, float* __restrict__ o)
{
    const int bh = blockIdx.x >> 2;
    const int cg = blockIdx.x & 3;
    const int b  = bh / NH, h = bh % NH;
    const int tid = threadIdx.x;
    const int s   = tid & 3;                 // k-split
    const int col = cg * 32 + (tid >> 2);    // v column

    __shared__ float qs[2][128], ks[2][128], gs[2][128];

    float S[32];
#pragma unroll
    for (int i = 0; i < 32; i++) S[i] = 0.f;

    const float scale = 0.08838834764831845f;   // 128^-0.5
    const size_t base0 = ((size_t)(b * SEQ) * NH + h) * (size_t)DK;

    {
        size_t base = base0 + tid;
        qs[0][tid] = q[base]; ks[0][tid] = k[base]; gs[0][tid] = ge[base];
    }
    __syncthreads();

    for (int t = 0; t < SEQ; t++) {
        const int buf = t & 1;
        float qn = 0.f, kn = 0.f, gn = 0.f;
        if (t + 1 < SEQ) {
            size_t nb = base0 + (size_t)(t + 1) * (NH * DK) + tid;
            qn = q[nb]; kn = k[nb]; gn = ge[nb];
        }
        size_t vb = ((size_t)(b * SEQ + t) * NH + h) * (size_t)DV + col;
        float vt = v[vb];
        float bt = beta[(size_t)(b * SEQ + t) * NH + h];

        const float4* k4 = (const float4*)&ks[buf][s * 32];
        const float4* g4 = (const float4*)&gs[buf][s * 32];
        float kreg[32];
        float kv = 0.f;
#pragma unroll
        for (int ii = 0; ii < 8; ii++) {
            float4 kk = k4[ii]; float4 gg = g4[ii];
            S[4*ii+0] *= gg.x; kv += kk.x * S[4*ii+0]; kreg[4*ii+0] = kk.x;
            S[4*ii+1] *= gg.y; kv += kk.y * S[4*ii+1]; kreg[4*ii+1] = kk.y;
            S[4*ii+2] *= gg.z; kv += kk.z * S[4*ii+2]; kreg[4*ii+2] = kk.z;
            S[4*ii+3] *= gg.w; kv += kk.w * S[4*ii+3]; kreg[4*ii+3] = kk.w;
        }
        kv += __shfl_xor_sync(0xFFFFFFFFu, kv, 1);
        kv += __shfl_xor_sync(0xFFFFFFFFu, kv, 2);
        float upd = (vt - kv) * bt;

        const float4* q4 = (const float4*)&qs[buf][s * 32];
        float ov = 0.f;
#pragma unroll
        for (int ii = 0; ii < 8; ii++) {
            float4 qq = q4[ii];
            S[4*ii+0] += kreg[4*ii+0] * upd; ov += qq.x * S[4*ii+0];
            S[4*ii+1] += kreg[4*ii+1] * upd; ov += qq.y * S[4*ii+1];
            S[4*ii+2] += kreg[4*ii+2] * upd; ov += qq.z * S[4*ii+2];
            S[4*ii+3] += kreg[4*ii+3] * upd; ov += qq.w * S[4*ii+3];
        }
        ov += __shfl_xor_sync(0xFFFFFFFFu, ov, 1);
        ov += __shfl_xor_sync(0xFFFFFFFFu, ov, 2);
        if (s == 0) o[vb] = ov * scale;

        if (t + 1 < SEQ) {
            int nbuf = buf ^ 1;
            qs[nbuf][tid] = qn; ks[nbuf][tid] = kn; gs[nbuf][tid] = gn;
        }
        __syncthreads();
    }
}

// ---------------------------------------------------------------------------
// Epilogue: gated RMSNorm (in-place on o)
// ---------------------------------------------------------------------------
__global__ __launch_bounds__(128) void epilogue_kernel(
    float* __restrict__ o, const float* __restrict__ gate,
    const float* __restrict__ bg, const float* __restrict__ onw)
{
    const int m = blockIdx.x;
    const int h = blockIdx.y;
    const int tid = threadIdx.x;
    size_t idx = ((size_t)m * NH + h) * (size_t)DV + tid;

    float ov = o[idx];
    float s = ov * ov;
#pragma unroll
    for (int off = 16; off > 0; off >>= 1)
        s += __shfl_xor_sync(0xFFFFFFFFu, s, off);

    __shared__ float ws[4];
    const int wd = tid >> 5, lane = tid & 31;
    if (lane == 0) ws[wd] = s;
    __syncthreads();
    float tot = ws[0] + ws[1] + ws[2] + ws[3];

    float r = rsqrtf(tot * (1.f / 128.f) + 1e-5f);
    float gv = gate[idx] + bg[h * DV + tid];
    float sig = 1.f / (1.f + expf(-gv));
    o[idx] = ov * r * onw[tid] * (gv * sig);
}

// ---------------------------------------------------------------------------
// kernel_launch
// ---------------------------------------------------------------------------
static inline void do_split(const float* src, __nv_bfloat16* hi,
                            __nv_bfloat16* lo, int n)
{
    int n4 = n >> 2;
    split_kernel<<<(n4 + 255) / 256, 256>>>(
        (const float4*)src, (__nv_bfloat162*)hi, (__nv_bfloat162*)lo, n4);
}

extern "C" void kernel_launch(void* const* d_in, const int* in_sizes, int n_in,
                              void* d_out, int out_size)
{
    const float* x       = (const float*)d_in[0];
    const float* Wq      = (const float*)d_in[1];
    const float* Wk      = (const float*)d_in[2];
    const float* Wv      = (const float*)d_in[3];
    const float* conv_q  = (const float*)d_in[4];
    const float* conv_k  = (const float*)d_in[5];
    const float* conv_v  = (const float*)d_in[6];
    const float* Wf1     = (const float*)d_in[7];
    const float* Wf2     = (const float*)d_in[8];
    const float* Wb      = (const float*)d_in[9];
    const float* A_log   = (const float*)d_in[10];
    const float* dt_bias = (const float*)d_in[11];
    const float* Wg      = (const float*)d_in[12];
    const float* bg      = (const float*)d_in[13];
    const float* o_norm_w= (const float*)d_in[14];
    const float* Wo      = (const float*)d_in[15];
    float* out = (float*)d_out;

    cudaFuncSetAttribute(tgemm_kernel,
                         cudaFuncAttributeMaxDynamicSharedMemorySize, GEMM_SMEM);

    float *qpre, *kpre, *vpre, *qb, *kb, *vb, *gateb, *gb, *ob, *f1b, *betab;
    cudaGetSymbolAddress((void**)&qpre,  g_qpre);
    cudaGetSymbolAddress((void**)&kpre,  g_kpre);
    cudaGetSymbolAddress((void**)&vpre,  g_vpre);
    cudaGetSymbolAddress((void**)&qb,    g_q);
    cudaGetSymbolAddress((void**)&kb,    g_k);
    cudaGetSymbolAddress((void**)&vb,    g_v);
    cudaGetSymbolAddress((void**)&gateb, g_gate);
    cudaGetSymbolAddress((void**)&gb,    g_g);
    cudaGetSymbolAddress((void**)&ob,    g_o);
    cudaGetSymbolAddress((void**)&f1b,   g_f1);
    cudaGetSymbolAddress((void**)&betab, g_beta);

    __nv_bfloat16 *xh, *xl, *oh, *ol, *wqh, *wql, *wkh, *wkl, *wvh, *wvl;
    __nv_bfloat16 *wgh, *wgl, *woh, *wol, *wf1h, *wf1l, *wf2h, *wf2l, *f1h, *f1l;
    cudaGetSymbolAddress((void**)&xh,   g_xh);   cudaGetSymbolAddress((void**)&xl,   g_xl);
    cudaGetSymbolAddress((void**)&oh,   g_oh);   cudaGetSymbolAddress((void**)&ol,   g_ol);
    cudaGetSymbolAddress((void**)&wqh,  g_wqh);  cudaGetSymbolAddress((void**)&wql,  g_wql);
    cudaGetSymbolAddress((void**)&wkh,  g_wkh);  cudaGetSymbolAddress((void**)&wkl,  g_wkl);
    cudaGetSymbolAddress((void**)&wvh,  g_wvh);  cudaGetSymbolAddress((void**)&wvl,  g_wvl);
    cudaGetSymbolAddress((void**)&wgh,  g_wgh);  cudaGetSymbolAddress((void**)&wgl,  g_wgl);
    cudaGetSymbolAddress((void**)&woh,  g_woh);  cudaGetSymbolAddress((void**)&wol,  g_wol);
    cudaGetSymbolAddress((void**)&wf1h, g_wf1h); cudaGetSymbolAddress((void**)&wf1l, g_wf1l);
    cudaGetSymbolAddress((void**)&wf2h, g_wf2h); cudaGetSymbolAddress((void**)&wf2l, g_wf2l);
    cudaGetSymbolAddress((void**)&f1h,  g_f1h);  cudaGetSymbolAddress((void**)&f1l,  g_f1l);

    // --- splits ---
    do_split(x,  xh,  xl,  NELEM);
    do_split(Wq, wqh, wql, WSZ);
    do_split(Wk, wkh, wkl, WSZ);
    do_split(Wv, wvh, wvl, WSZ);
    do_split(Wg, wgh, wgl, WSZ);
    do_split(Wo, woh, wol, WSZ);
    do_split(Wf1, wf1h, wf1l, DIM * DV);
    do_split(Wf2, wf2h, wf2l, DV * DIM);

    dim3 gBig(DIM / 128, MTOT / 128);   // (16, 32)
    dim3 gF1(DV / 128, MTOT / 128);     // (1, 32)

    // --- projections (tensor core via mma.sync) ---
    tgemm_kernel<<<gBig, 256, GEMM_SMEM>>>(xh, xl, wqh, wql, qpre, MTOT, DIM, DIM);
    tgemm_kernel<<<gBig, 256, GEMM_SMEM>>>(xh, xl, wkh, wkl, kpre, MTOT, DIM, DIM);
    tgemm_kernel<<<gBig, 256, GEMM_SMEM>>>(xh, xl, wvh, wvl, vpre, MTOT, DIM, DIM);
    tgemm_kernel<<<gBig, 256, GEMM_SMEM>>>(xh, xl, wgh, wgl, gateb, MTOT, DIM, DIM);
    tgemm_kernel<<<gF1,  256, GEMM_SMEM>>>(xh, xl, wf1h, wf1l, f1b, MTOT, DV, DIM);

    do_split(f1b, f1h, f1l, MTOT * DV);
    tgemm_kernel<<<gBig, 256, GEMM_SMEM>>>(f1h, f1l, wf2h, wf2l, gb, MTOT, DIM, DV);

    beta_kernel<<<MTOT, 128>>>(x, Wb, betab);

    // --- conv + silu (+ l2norm for q,k) ---
    dim3 gConv(SEQ / 32, DIM / 128, BATCH);
    conv_kernel<true ><<<gConv, 128>>>(qpre, conv_q, qb);
    conv_kernel<true ><<<gConv, 128>>>(kpre, conv_k, kb);
    conv_kernel<false><<<gConv, 128>>>(vpre, conv_v, vb);

    // --- decay gates ---
    gexp_kernel<<<NELEM / 256, 256>>>(gb, A_log, dt_bias, NELEM);

    // --- delta-rule scan (128 blocks) ---
    scan_kernel<<<BATCH * NH * 4, 128>>>(qb, kb, vb, gb, betab, ob);

    // --- gated RMSNorm epilogue ---
    dim3 gEpi(MTOT, NH);
    epilogue_kernel<<<gEpi, 128>>>(ob, gateb, bg, o_norm_w);

    // --- output projection ---
    do_split(ob, oh, ol, NELEM);
    tgemm_kernel<<<gBig, 256, GEMM_SMEM>>>(oh, ol, woh, wol, out, MTOT, DIM, DIM);
}